// round 9
// baseline (speedup 1.0000x reference)
#include <cuda_runtime.h>

#define N   512
#define DIM 384
#define BK  32
#define NTL 12          // DIM / BK
typedef unsigned long long ull;

// Scratch (device globals per allocation-free rule)
__device__ float    g_D[N * N];    // pairwise distances, diag = 1e6
__device__ float    g_prec[N];     // per-query soft precision
__device__ unsigned g_ctr1;        // monotonic ticket: grid barrier (replay-safe)
__device__ unsigned g_ctr2;        // monotonic ticket: completion count

// Branchless full-range sigmoid (exp underflow -> exact 0/1 saturation)
__device__ __forceinline__ float sigmoid_nb(float x) {
    float e = __expf(-fabsf(x));
    float p = __fdividef(1.f, 1.f + e);
    return (x >= 0.f) ? p : 1.f - p;
}
__device__ __forceinline__ void fma2(ull& d, ull a, ull b) {
    asm("fma.rn.f32x2 %0, %1, %2, %0;" : "+l"(d) : "l"(a), "l"(b));
}
__device__ __forceinline__ float2 unpack2(ull v) {
    float2 r;
    asm("mov.b64 {%0, %1}, %2;" : "=f"(r.x), "=f"(r.y) : "l"(v));
    return r;
}

#define SA_STR 68
#define SB_STR 68
#define SMEM_FLOATS (BK * SA_STR + BK * SB_STR)   // 4352; phase2 needs 2560

__global__ void __launch_bounds__(256, 1)
k_fused(const float* __restrict__ emb, const int* __restrict__ labels,
        float* __restrict__ out)
{
    __shared__ __align__(16) float smem[SMEM_FLOATS];
    __shared__ float snA[32];
    __shared__ float snB[64];
    __shared__ float wnum[8];
    __shared__ int   wcnt[8];
    __shared__ float swr[8];
    __shared__ int   s_done;

    const int t = threadIdx.x;
    const int b = blockIdx.x;

    // ================= Phase 1: fused Gram -> distance tile (R8-proven) =================
    {
        float* sa = smem;                 // A dup'd k-major, stride 68
        float* sb = smem + BK * SA_STR;   // B k-major, stride 68

        const int q0 = (b >> 3) * 32;
        const int m0 = (b & 7) * 64;
        const int rA = t >> 3, cA = (t & 7) * 4;
        const int rB = t >> 2, cB = (t & 3) * 8;
        const float* pA = emb + (size_t)(q0 + rA) * DIM + cA;
        const float* pB = emb + (size_t)(m0 + rB) * DIM + cB;
        const int tx = t & 15, ty = t >> 4;

        ull acc00 = 0, acc01 = 0, acc10 = 0, acc11 = 0;
        float nA = 0.f, nB = 0.f;

        float4 a0 = *(const float4*)pA;
        float4 b0 = *(const float4*)pB;
        float4 b1 = *(const float4*)(pB + 4);

#pragma unroll 1
        for (int tt = 0; tt < NTL; tt++) {
            nA = fmaf(a0.x,a0.x,fmaf(a0.y,a0.y,fmaf(a0.z,a0.z,fmaf(a0.w,a0.w,nA))));
            nB = fmaf(b0.x,b0.x,fmaf(b0.y,b0.y,fmaf(b0.z,b0.z,fmaf(b0.w,b0.w,nB))));
            nB = fmaf(b1.x,b1.x,fmaf(b1.y,b1.y,fmaf(b1.z,b1.z,fmaf(b1.w,b1.w,nB))));

            *(float2*)&sa[(cA+0)*SA_STR + 2*rA] = make_float2(a0.x, a0.x);
            *(float2*)&sa[(cA+1)*SA_STR + 2*rA] = make_float2(a0.y, a0.y);
            *(float2*)&sa[(cA+2)*SA_STR + 2*rA] = make_float2(a0.z, a0.z);
            *(float2*)&sa[(cA+3)*SA_STR + 2*rA] = make_float2(a0.w, a0.w);
            sb[(cB+0)*SB_STR + rB] = b0.x; sb[(cB+1)*SB_STR + rB] = b0.y;
            sb[(cB+2)*SB_STR + rB] = b0.z; sb[(cB+3)*SB_STR + rB] = b0.w;
            sb[(cB+4)*SB_STR + rB] = b1.x; sb[(cB+5)*SB_STR + rB] = b1.y;
            sb[(cB+6)*SB_STR + rB] = b1.z; sb[(cB+7)*SB_STR + rB] = b1.w;
            __syncthreads();

            if (tt + 1 < NTL) {
                a0 = *(const float4*)(pA + (tt + 1) * BK);
                b0 = *(const float4*)(pB + (tt + 1) * BK);
                b1 = *(const float4*)(pB + (tt + 1) * BK + 4);
            }

#pragma unroll
            for (int k = 0; k < BK; k++) {
                ulonglong2 aav = *(const ulonglong2*)&sa[k * SA_STR + 4 * ty];
                ulonglong2 bbv = *(const ulonglong2*)&sb[k * SB_STR + 4 * tx];
                fma2(acc00, aav.x, bbv.x);
                fma2(acc01, aav.x, bbv.y);
                fma2(acc10, aav.y, bbv.x);
                fma2(acc11, aav.y, bbv.y);
            }
            __syncthreads();
        }

        nA += __shfl_xor_sync(0xffffffffu, nA, 1);
        nA += __shfl_xor_sync(0xffffffffu, nA, 2);
        nA += __shfl_xor_sync(0xffffffffu, nA, 4);
        if ((t & 7) == 0) snA[rA] = nA;
        nB += __shfl_xor_sync(0xffffffffu, nB, 1);
        nB += __shfl_xor_sync(0xffffffffu, nB, 2);
        if ((t & 3) == 0) snB[rB] = nB;
        __syncthreads();

        float2 c00 = unpack2(acc00), c01 = unpack2(acc01);
        float2 c10 = unpack2(acc10), c11 = unpack2(acc11);
        float accs[2][4] = {{c00.x, c00.y, c01.x, c01.y},
                            {c10.x, c10.y, c11.x, c11.y}};
#pragma unroll
        for (int i = 0; i < 2; i++) {
            int q  = q0 + 2 * ty + i;
            int mb = m0 + 4 * tx;
            float nq = snA[2 * ty + i];
            float dv[4];
#pragma unroll
            for (int c = 0; c < 4; c++) {
                float d2 = nq + snB[4 * tx + c] - 2.f * accs[i][c];
                dv[c] = (q == mb + c) ? 1e6f : sqrtf(fmaxf(d2, 1e-12f));
            }
            *(float4*)&g_D[(size_t)q * N + mb] = make_float4(dv[0], dv[1], dv[2], dv[3]);
        }
    }

    // ================= Grid barrier (replay-safe monotonic ticket) =================
    __syncthreads();
    if (t == 0) {
        __threadfence();
        unsigned tk = atomicAdd(&g_ctr1, 1u);
        unsigned target = (tk / 128u) * 128u + 128u;
        while (atomicAdd(&g_ctr1, 0u) < target) __nanosleep(32);
        __threadfence();
    }
    __syncthreads();

    // ================= Phase 2: soft precision, 4 queries/block, 8 warps =================
    {
        float* sd   = smem;                  // 4 rows x 512 floats (aliases gram tiles)
        int*   slab = (int*)(smem + 4 * N);  // 512 labels

        const int q0b  = blockIdx.x * 4;
        const int lane = t & 31;
        const int w    = t >> 5;

        // 4 rows = 512 float4 -> 2 per thread; labels 128 int4
        const float4* src = (const float4*)(g_D + (size_t)q0b * N);
        ((float4*)sd)[t]       = __ldcg(&src[t]);
        ((float4*)sd)[t + 256] = __ldcg(&src[t + 256]);
        if (t < 128) ((int4*)slab)[t] = ((const int4*)labels)[t];
        __syncthreads();

        const int   qsel = w & 3;
        const int   q    = q0b + qsel;
        const int   lq   = slab[q];
        const float* row = sd + qsel * N;
        const int   jb   = (w >> 2) * 256;   // half-range per warp

        // row values this lane compares against: registers, loaded once
        float rv[16];
#pragma unroll
        for (int i = 0; i < 16; i++) rv[i] = row[lane + 32 * i];

        float num = 0.f;
        int   cnt = 0;
#pragma unroll
        for (int c = 0; c < 8; c++) {
            int j = jb + c * 32 + lane;
            bool f = (j != q) && (slab[j] == lq);
            unsigned bm = __ballot_sync(0xffffffffu, f);
            cnt += __popc(bm);
            while (bm) {                     // ascending j: deterministic
                int bit = __ffs(bm) - 1;
                bm &= bm - 1;
                float dj = row[jb + c * 32 + bit];
                float part = 0.f;
#pragma unroll
                for (int i = 0; i < 16; i++) {
                    float x = (dj - rv[i]) * 100.0f;     // 1/T2
                    float stp = (x >= 0.f) ? 1.f : 0.f;
                    part += stp;
                    if (fabsf(x) < 18.f)                 // rare near-tie fixup
                        part += sigmoid_nb(x) - stp;
                }
#pragma unroll
                for (int o = 16; o; o >>= 1)
                    part += __shfl_xor_sync(0xffffffffu, part, o);
                num += sigmoid_nb(5.0f - part);          // K=5, T1=1
            }
        }
        if (lane == 0) { wnum[w] = num; wcnt[w] = cnt; }
        __syncthreads();

        if (t < 4) {   // fixed half-order: deterministic
            float s = wnum[t] + wnum[4 + t];
            int   c = wcnt[t] + wcnt[4 + t];
            g_prec[q0b + t] = s / fminf((float)c, 5.0f); // 0/0 -> NaN like reference
        }
    }

    // ================= Phase 3: last-arriving block does the fixed-order mean =================
    __syncthreads();
    if (t == 0) {
        __threadfence();
        unsigned tk = atomicAdd(&g_ctr2, 1u);
        s_done = ((tk & 127u) == 127u) ? 1 : 0;
    }
    __syncthreads();

    if (s_done) {
        __threadfence();
        const int lane = t & 31;
        const int w    = t >> 5;
        float v = __ldcg(&g_prec[t]) + __ldcg(&g_prec[t + 256]);
#pragma unroll
        for (int o = 16; o; o >>= 1)
            v += __shfl_xor_sync(0xffffffffu, v, o);
        if (lane == 0) swr[w] = v;
        __syncthreads();
        if (t == 0) {
            float s = 0.f;
#pragma unroll
            for (int i = 0; i < 8; i++) s += swr[i];
            out[0] = 1.0f - s / (float)N;
        }
    }
}

extern "C" void kernel_launch(void* const* d_in, const int* in_sizes, int n_in,
                              void* d_out, int out_size) {
    const float* emb    = (const float*)d_in[0];
    const int*   labels = (const int*)d_in[1];
    k_fused<<<128, 256>>>(emb, labels, (float*)d_out);
}